// round 2
// baseline (speedup 1.0000x reference)
#include <cuda_runtime.h>

#define BB 4
#define SS 1024
#define DDIM 768
#define HH 12
#define EE 8
#define HID 3072
#define DH 64
#define NTOK (BB*SS)
#define CAP (NTOK*2)

// ---------------- scratch (device globals: no allocation allowed) ----------------
__device__ float g_a[NTOK*DDIM];     // ln_attn(x)
__device__ float g_q[NTOK*DDIM];
__device__ float g_k[NTOK*DDIM];
__device__ float g_v[NTOK*DDIM];
__device__ float g_ctx[NTOK*DDIM];
__device__ float g_xa[NTOK*DDIM];    // x + attn_out
__device__ float g_h[NTOK*DDIM];     // ln_ff(xa)
__device__ float g_y1[CAP*HID];      // expert hidden (per token-slot pair)
__device__ float g_o2[CAP*DDIM];     // expert out (per pair)
__device__ float g_sc[CAP];          // top-2 softmax weights (per pair)
__device__ int   g_cnt[EE];
__device__ int   g_list[EE*CAP];

// ---------------- block reduce ----------------
__device__ __forceinline__ float blockReduceSum(float v) {
    __shared__ float sh[33];
    __syncthreads();                      // protect sh reuse across calls
    int lane = threadIdx.x & 31, wid = threadIdx.x >> 5;
    #pragma unroll
    for (int o = 16; o > 0; o >>= 1) v += __shfl_down_sync(0xffffffffu, v, o);
    if (lane == 0) sh[wid] = v;
    __syncthreads();
    float r = (threadIdx.x < (blockDim.x >> 5)) ? sh[threadIdx.x] : 0.f;
    if (wid == 0) {
        #pragma unroll
        for (int o = 16; o > 0; o >>= 1) r += __shfl_down_sync(0xffffffffu, r, o);
        if (lane == 0) sh[32] = r;
    }
    __syncthreads();
    return sh[32];
}

// ---------------- layernorm: one block per row, D=768, 256 threads ----------------
__global__ void ln_kernel(const float* __restrict__ x, const float* __restrict__ g,
                          const float* __restrict__ b, float* __restrict__ out) {
    int row = blockIdx.x;
    const float* xr = x + (size_t)row * DDIM;
    float v[3];
    float s = 0.f;
    #pragma unroll
    for (int i = 0; i < 3; i++) { v[i] = xr[threadIdx.x + i*256]; s += v[i]; }
    s = blockReduceSum(s);
    float mean = s * (1.f / DDIM);
    float vs = 0.f;
    #pragma unroll
    for (int i = 0; i < 3; i++) { float d = v[i] - mean; vs += d*d; }
    vs = blockReduceSum(vs);
    float rstd = rsqrtf(vs * (1.f / DDIM) + 1e-5f);
    #pragma unroll
    for (int i = 0; i < 3; i++) {
        int d = threadIdx.x + i*256;
        out[(size_t)row*DDIM + d] = (v[i] - mean) * rstd * g[d] + b[d];
    }
}

// ---------------- SGEMM: 128x128x8 tile, 8x8 per thread, 256 threads ----------------
// GATHER: rows come from per-expert pair lists (blockIdx.z = expert)
// AROW_PAIR: A row index = pair id (else pair>>1 = token id)
// RELU / RESID: epilogue options
template<bool GATHER, bool AROW_PAIR, bool RELU, bool RESID>
__global__ __launch_bounds__(256) void sgemm_k(
    int M, int N, int K,
    const float* __restrict__ A, int lda,
    const float* __restrict__ Bm,
    const float* __restrict__ bias,
    const float* __restrict__ resid,
    float* __restrict__ C, int ldc,
    const int* __restrict__ rowlist,
    const int* __restrict__ cnt)
{
    __shared__ float As[8][128];
    __shared__ float Bs[8][128];
    __shared__ int rowsS[128];

    if (GATHER) {
        int e = blockIdx.z;
        Bm      += (size_t)e * K * N;
        bias    += (size_t)e * N;
        rowlist += (size_t)e * CAP;
        cnt     += e;
    }
    int m0 = blockIdx.y * 128, n0 = blockIdx.x * 128;
    int tid = threadIdx.x;

    if (GATHER) {
        int Meff = *cnt;
        if (m0 >= Meff) return;
        for (int r = tid; r < 128; r += 256) {
            int gidx = m0 + r;
            rowsS[r] = (gidx < Meff) ? rowlist[gidx] : -1;
        }
        __syncthreads();
    }

    int aRow = tid >> 1;
    int aCol = (tid & 1) << 2;
    int bRow = tid >> 5;
    int bCol = (tid & 31) << 2;

    const float* Aload;
    if (GATHER) {
        int pr = rowsS[aRow];
        if (pr < 0) Aload = nullptr;
        else {
            int ar = AROW_PAIR ? pr : (pr >> 1);
            Aload = A + (size_t)ar * lda;
        }
    } else {
        Aload = A + (size_t)(m0 + aRow) * lda;
    }
    const float* Bload = Bm + (size_t)bRow * N + n0 + bCol;

    float acc[8][8];
    #pragma unroll
    for (int i = 0; i < 8; i++)
        #pragma unroll
        for (int j = 0; j < 8; j++) acc[i][j] = 0.f;

    int trow = (tid >> 4) << 3;
    int tcol = (tid & 15) << 3;

    for (int k0 = 0; k0 < K; k0 += 8) {
        float4 av = Aload ? *(const float4*)(Aload + k0 + aCol) : make_float4(0,0,0,0);
        float4 bv = *(const float4*)(Bload + (size_t)k0 * N);
        __syncthreads();
        As[aCol+0][aRow] = av.x; As[aCol+1][aRow] = av.y;
        As[aCol+2][aRow] = av.z; As[aCol+3][aRow] = av.w;
        *(float4*)&Bs[bRow][bCol] = bv;
        __syncthreads();
        #pragma unroll
        for (int kk = 0; kk < 8; kk++) {
            float ra[8], rb[8];
            *(float4*)&ra[0] = *(float4*)&As[kk][trow];
            *(float4*)&ra[4] = *(float4*)&As[kk][trow+4];
            *(float4*)&rb[0] = *(float4*)&Bs[kk][tcol];
            *(float4*)&rb[4] = *(float4*)&Bs[kk][tcol+4];
            #pragma unroll
            for (int i = 0; i < 8; i++)
                #pragma unroll
                for (int j = 0; j < 8; j++)
                    acc[i][j] += ra[i] * rb[j];
        }
    }

    float bb[8];
    {
        float4 b0 = *(const float4*)(bias + n0 + tcol);
        float4 b1 = *(const float4*)(bias + n0 + tcol + 4);
        bb[0]=b0.x; bb[1]=b0.y; bb[2]=b0.z; bb[3]=b0.w;
        bb[4]=b1.x; bb[5]=b1.y; bb[6]=b1.z; bb[7]=b1.w;
    }
    #pragma unroll
    for (int i = 0; i < 8; i++) {
        int crow;
        if (GATHER) {
            int pr = rowsS[trow + i];
            if (pr < 0) continue;
            crow = pr;
        } else {
            crow = m0 + trow + i;
        }
        float ov[8];
        #pragma unroll
        for (int j = 0; j < 8; j++) {
            float x = acc[i][j] + bb[j];
            if (RELU) x = fmaxf(x, 0.f);
            ov[j] = x;
        }
        float* cp = C + (size_t)crow * ldc + n0 + tcol;
        if (RESID) {
            const float* rp = resid + (size_t)crow * ldc + n0 + tcol;
            float4 r0 = *(const float4*)rp, r1 = *(const float4*)(rp + 4);
            ov[0]+=r0.x; ov[1]+=r0.y; ov[2]+=r0.z; ov[3]+=r0.w;
            ov[4]+=r1.x; ov[5]+=r1.y; ov[6]+=r1.z; ov[7]+=r1.w;
        }
        *(float4*)cp       = make_float4(ov[0], ov[1], ov[2], ov[3]);
        *(float4*)(cp + 4) = make_float4(ov[4], ov[5], ov[6], ov[7]);
    }
}

// ---------------- flash attention (causal), one q-row per thread ----------------
// grid (S/128, H, B), 128 threads. K/V tiles of 32 rows in shared.
__global__ void __launch_bounds__(128, 1) attn_kernel(
    const float* __restrict__ q, const float* __restrict__ k,
    const float* __restrict__ v, float* __restrict__ ctx)
{
    int qt = blockIdx.x, h = blockIdx.y, b = blockIdx.z;
    int tid = threadIdx.x;
    int qidx = qt * 128 + tid;

    __shared__ float4 ksh[32*16];
    __shared__ float4 vsh[32*16];

    float4 qr[16], acc[16];
    const float4* qp = (const float4*)(q + (size_t)(b*SS + qidx)*DDIM + h*DH);
    #pragma unroll
    for (int j = 0; j < 16; j++) {
        float4 t = qp[j];
        qr[j] = make_float4(t.x*0.125f, t.y*0.125f, t.z*0.125f, t.w*0.125f);
        acc[j] = make_float4(0,0,0,0);
    }
    float m = -3.0e38f, l = 0.f;

    int kend = qt*128 + 128;
    if (kend > SS) kend = SS;
    for (int kt = 0; kt < kend; kt += 32) {
        __syncthreads();
        for (int i = tid; i < 512; i += 128) {
            int r = i >> 4, c = i & 15;
            size_t base = (size_t)(b*SS + kt + r)*DDIM + h*DH;
            ksh[i] = *((const float4*)(k + base) + c);
            vsh[i] = *((const float4*)(v + base) + c);
        }
        __syncthreads();

        float s[32];
        float tm = -3.0e38f;
        #pragma unroll
        for (int kk = 0; kk < 32; kk++) {
            const float4* kr = &ksh[kk*16];
            float d = 0.f;
            #pragma unroll
            for (int j = 0; j < 16; j++) {
                float4 kv = kr[j];
                d += qr[j].x*kv.x + qr[j].y*kv.y + qr[j].z*kv.z + qr[j].w*kv.w;
            }
            s[kk] = (kt + kk <= qidx) ? d : -1e9f;
            tm = fmaxf(tm, s[kk]);
        }
        float nm = fmaxf(m, tm);
        float c = __expf(m - nm);
        l *= c;
        #pragma unroll
        for (int j = 0; j < 16; j++) {
            acc[j].x *= c; acc[j].y *= c; acc[j].z *= c; acc[j].w *= c;
        }
        #pragma unroll
        for (int kk = 0; kk < 32; kk++) {
            float p = __expf(s[kk] - nm);
            l += p;
            const float4* vr = &vsh[kk*16];
            #pragma unroll
            for (int j = 0; j < 16; j++) {
                float4 vv = vr[j];
                acc[j].x += p*vv.x; acc[j].y += p*vv.y;
                acc[j].z += p*vv.z; acc[j].w += p*vv.w;
            }
        }
        m = nm;
    }
    float inv = 1.f / l;
    float4* op = (float4*)(ctx + (size_t)(b*SS + qidx)*DDIM + h*DH);
    #pragma unroll
    for (int j = 0; j < 16; j++)
        op[j] = make_float4(acc[j].x*inv, acc[j].y*inv, acc[j].z*inv, acc[j].w*inv);
}

// ---------------- gate: logits, top-2, softmax, expert lists ----------------
__global__ void zero_cnt_kernel(int* cnt) {
    if (threadIdx.x < EE) cnt[threadIdx.x] = 0;
}

__global__ void gate_kernel(const float* __restrict__ h, const float* __restrict__ gw,
                            const float* __restrict__ gb, float* __restrict__ sc,
                            int* __restrict__ cnt, int* __restrict__ list)
{
    int warp = (blockIdx.x * blockDim.x + threadIdx.x) >> 5;
    if (warp >= NTOK) return;
    int lane = threadIdx.x & 31;
    float a[8] = {0,0,0,0,0,0,0,0};
    const float* hr = h + (size_t)warp * DDIM;
    for (int d = lane; d < DDIM; d += 32) {
        float hv = hr[d];
        float4 w0 = *(const float4*)(gw + (size_t)d*EE);
        float4 w1 = *(const float4*)(gw + (size_t)d*EE + 4);
        a[0]+=hv*w0.x; a[1]+=hv*w0.y; a[2]+=hv*w0.z; a[3]+=hv*w0.w;
        a[4]+=hv*w1.x; a[5]+=hv*w1.y; a[6]+=hv*w1.z; a[7]+=hv*w1.w;
    }
    #pragma unroll
    for (int e = 0; e < 8; e++)
        #pragma unroll
        for (int o = 16; o > 0; o >>= 1)
            a[e] += __shfl_down_sync(0xffffffffu, a[e], o);
    if (lane == 0) {
        float lg[8];
        #pragma unroll
        for (int e = 0; e < 8; e++) lg[e] = a[e] + gb[e];
        int i0 = 0; float v0 = lg[0];
        #pragma unroll
        for (int e = 1; e < 8; e++) if (lg[e] > v0) { v0 = lg[e]; i0 = e; }
        int i1 = -1; float v1 = -3.0e38f;
        #pragma unroll
        for (int e = 0; e < 8; e++) if (e != i0 && lg[e] > v1) { v1 = lg[e]; i1 = e; }
        float e1 = __expf(v1 - v0);
        float s0 = 1.f / (1.f + e1);
        float s1 = e1 * s0;
        sc[2*warp]   = s0;
        sc[2*warp+1] = s1;
        int p0 = atomicAdd(&cnt[i0], 1);
        list[(size_t)i0*CAP + p0] = 2*warp;
        int p1 = atomicAdd(&cnt[i1], 1);
        list[(size_t)i1*CAP + p1] = 2*warp + 1;
    }
}

// ---------------- combine: core = sc0*o0 + sc1*o1; ln(h+core); out = xa + moe ----------------
__global__ void combine_kernel(const float* __restrict__ h, const float* __restrict__ o2,
                               const float* __restrict__ sc, const float* __restrict__ xa,
                               const float* __restrict__ g, const float* __restrict__ b,
                               float* __restrict__ out)
{
    int t = blockIdx.x;
    const float* hr = h + (size_t)t*DDIM;
    const float* r0 = o2 + (size_t)(2*t)*DDIM;
    const float* r1 = o2 + (size_t)(2*t+1)*DDIM;
    float s0 = sc[2*t], s1 = sc[2*t+1];
    float tv[3];
    float s = 0.f;
    #pragma unroll
    for (int i = 0; i < 3; i++) {
        int d = threadIdx.x + i*256;
        tv[i] = hr[d] + s0*r0[d] + s1*r1[d];
        s += tv[i];
    }
    s = blockReduceSum(s);
    float mean = s * (1.f / DDIM);
    float vs = 0.f;
    #pragma unroll
    for (int i = 0; i < 3; i++) { float d = tv[i] - mean; vs += d*d; }
    vs = blockReduceSum(vs);
    float rstd = rsqrtf(vs * (1.f / DDIM) + 1e-5f);
    #pragma unroll
    for (int i = 0; i < 3; i++) {
        int d = threadIdx.x + i*256;
        out[(size_t)t*DDIM + d] = xa[(size_t)t*DDIM + d] + (tv[i] - mean)*rstd*g[d] + b[d];
    }
}

// ---------------- launch ----------------
extern "C" void kernel_launch(void* const* d_in, const int* in_sizes, int n_in,
                              void* d_out, int out_size)
{
    const float* x        = (const float*)d_in[0];
    // d_in[1] = mask (implicit causal, unused)
    const float* ln_a_g   = (const float*)d_in[2];
    const float* ln_a_b   = (const float*)d_in[3];
    const float* wq       = (const float*)d_in[4];
    const float* bq       = (const float*)d_in[5];
    const float* wk       = (const float*)d_in[6];
    const float* bk       = (const float*)d_in[7];
    const float* wv       = (const float*)d_in[8];
    const float* bv       = (const float*)d_in[9];
    const float* wo       = (const float*)d_in[10];
    const float* bo       = (const float*)d_in[11];
    const float* ln_f_g   = (const float*)d_in[12];
    const float* ln_f_b   = (const float*)d_in[13];
    const float* gate_w   = (const float*)d_in[14];
    const float* gate_b   = (const float*)d_in[15];
    const float* w1       = (const float*)d_in[16];
    const float* b1       = (const float*)d_in[17];
    const float* w2       = (const float*)d_in[18];
    const float* b2       = (const float*)d_in[19];
    const float* moe_g    = (const float*)d_in[20];
    const float* moe_b    = (const float*)d_in[21];
    float* out = (float*)d_out;

    float *a, *qb, *kb, *vb, *ctx, *xa, *h, *y1, *o2, *sc;
    int *cnt, *list;
    cudaGetSymbolAddress((void**)&a,   g_a);
    cudaGetSymbolAddress((void**)&qb,  g_q);
    cudaGetSymbolAddress((void**)&kb,  g_k);
    cudaGetSymbolAddress((void**)&vb,  g_v);
    cudaGetSymbolAddress((void**)&ctx, g_ctx);
    cudaGetSymbolAddress((void**)&xa,  g_xa);
    cudaGetSymbolAddress((void**)&h,   g_h);
    cudaGetSymbolAddress((void**)&y1,  g_y1);
    cudaGetSymbolAddress((void**)&o2,  g_o2);
    cudaGetSymbolAddress((void**)&sc,  g_sc);
    cudaGetSymbolAddress((void**)&cnt, g_cnt);
    cudaGetSymbolAddress((void**)&list,g_list);

    // 1) a = ln_attn(x)
    ln_kernel<<<NTOK, 256>>>(x, ln_a_g, ln_a_b, a);

    // 2) q,k,v = a @ W + b
    dim3 gQKV(DDIM/128, NTOK/128, 1);
    sgemm_k<false,false,false,false><<<gQKV, 256>>>(NTOK, DDIM, DDIM, a, DDIM, wq, bq, nullptr, qb, DDIM, nullptr, nullptr);
    sgemm_k<false,false,false,false><<<gQKV, 256>>>(NTOK, DDIM, DDIM, a, DDIM, wk, bk, nullptr, kb, DDIM, nullptr, nullptr);
    sgemm_k<false,false,false,false><<<gQKV, 256>>>(NTOK, DDIM, DDIM, a, DDIM, wv, bv, nullptr, vb, DDIM, nullptr, nullptr);

    // 3) flash attention (causal)
    attn_kernel<<<dim3(SS/128, HH, BB), 128>>>(qb, kb, vb, ctx);

    // 4) xa = x + ctx @ wo + bo
    sgemm_k<false,false,false,true><<<gQKV, 256>>>(NTOK, DDIM, DDIM, ctx, DDIM, wo, bo, x, xa, DDIM, nullptr, nullptr);

    // 5) h = ln_ff(xa)
    ln_kernel<<<NTOK, 256>>>(xa, ln_f_g, ln_f_b, h);

    // 6) gate: top-2 per token + per-expert pair lists
    zero_cnt_kernel<<<1, 32>>>(cnt);
    gate_kernel<<<NTOK/8, 256>>>(h, gate_w, gate_b, sc, cnt, list);

    // 7) expert GEMM1: y1[pair] = relu(h[token] @ w1[e] + b1[e])
    sgemm_k<true,false,true,false><<<dim3(HID/128, CAP/128, EE), 256>>>(
        CAP, HID, DDIM, h, DDIM, w1, b1, nullptr, y1, HID, list, cnt);

    // 8) expert GEMM2: o2[pair] = y1[pair] @ w2[e] + b2[e]
    sgemm_k<true,true,false,false><<<dim3(DDIM/128, CAP/128, EE), 256>>>(
        CAP, DDIM, HID, y1, HID, w2, b2, nullptr, o2, DDIM, list, cnt);

    // 9) combine + post-LN + final residual
    combine_kernel<<<NTOK, 256>>>(h, o2, sc, xa, moe_g, moe_b, out);
}

// round 3
// speedup vs baseline: 2.3035x; 2.3035x over previous
#include <cuda_runtime.h>

#define BB 4
#define SS 1024
#define DDIM 768
#define HH 12
#define EE 8
#define HID 3072
#define DH 64
#define NTOK (BB*SS)
#define CAP (NTOK*2)

// ---------------- scratch (device globals: no allocation allowed) ----------------
__device__ float g_a[NTOK*DDIM];     // ln_attn(x)
__device__ float g_q[NTOK*DDIM];
__device__ float g_k[NTOK*DDIM];
__device__ float g_v[NTOK*DDIM];
__device__ float g_ctx[NTOK*DDIM];
__device__ float g_xa[NTOK*DDIM];    // x + attn_out
__device__ float g_h[NTOK*DDIM];     // ln_ff(xa)
__device__ float g_y1[CAP*HID];      // expert hidden (per token-slot pair)
__device__ float g_o2[CAP*DDIM];     // expert out (per pair)
__device__ float g_sc[CAP];          // top-2 softmax weights (per pair)
__device__ int   g_cnt[EE];
__device__ int   g_list[EE*CAP];

// ---------------- helpers ----------------
__device__ __forceinline__ unsigned f2tf32(float x) {
    unsigned u; asm("cvt.rna.tf32.f32 %0, %1;" : "=r"(u) : "f"(x)); return u;
}

__device__ __forceinline__ void mma_tf32(float c[4], const unsigned a[4], const unsigned b[2]) {
    asm volatile("mma.sync.aligned.m16n8k8.row.col.f32.tf32.tf32.f32 "
        "{%0,%1,%2,%3}, {%4,%5,%6,%7}, {%8,%9}, {%0,%1,%2,%3};"
        : "+f"(c[0]), "+f"(c[1]), "+f"(c[2]), "+f"(c[3])
        : "r"(a[0]), "r"(a[1]), "r"(a[2]), "r"(a[3]), "r"(b[0]), "r"(b[1]));
}

__device__ __forceinline__ float blockReduceSum(float v) {
    __shared__ float sh[33];
    __syncthreads();
    int lane = threadIdx.x & 31, wid = threadIdx.x >> 5;
    #pragma unroll
    for (int o = 16; o > 0; o >>= 1) v += __shfl_down_sync(0xffffffffu, v, o);
    if (lane == 0) sh[wid] = v;
    __syncthreads();
    float r = (threadIdx.x < (blockDim.x >> 5)) ? sh[threadIdx.x] : 0.f;
    if (wid == 0) {
        #pragma unroll
        for (int o = 16; o > 0; o >>= 1) r += __shfl_down_sync(0xffffffffu, r, o);
        if (lane == 0) sh[32] = r;
    }
    __syncthreads();
    return sh[32];
}

// ---------------- layernorm ----------------
__global__ void ln_kernel(const float* __restrict__ x, const float* __restrict__ g,
                          const float* __restrict__ b, float* __restrict__ out) {
    int row = blockIdx.x;
    const float* xr = x + (size_t)row * DDIM;
    float v[3];
    float s = 0.f;
    #pragma unroll
    for (int i = 0; i < 3; i++) { v[i] = xr[threadIdx.x + i*256]; s += v[i]; }
    s = blockReduceSum(s);
    float mean = s * (1.f / DDIM);
    float vs = 0.f;
    #pragma unroll
    for (int i = 0; i < 3; i++) { float d = v[i] - mean; vs += d*d; }
    vs = blockReduceSum(vs);
    float rstd = rsqrtf(vs * (1.f / DDIM) + 1e-5f);
    #pragma unroll
    for (int i = 0; i < 3; i++) {
        int d = threadIdx.x + i*256;
        out[(size_t)row*DDIM + d] = (v[i] - mean) * rstd * g[d] + b[d];
    }
}

// ---------------- TF32 tensor-core GEMM ----------------
// 128x128 block tile, BK=16, 8 warps (4 along M x 2 along N), warp tile 32x64.
// A: [M][K] row-major (optionally gathered rows). B: [K][N] row-major.
// Shared: As[m][k] pad 20, Bs[k][n] pad 136 (conflict-free fragment loads).
template<bool GATHER, bool AROW_PAIR, bool RELU, bool RESID>
__global__ __launch_bounds__(256, 2) void tgemm_k(
    int M, int N, int K,
    const float* __restrict__ A, int lda,
    const float* __restrict__ Bm,
    const float* __restrict__ bias,
    const float* __restrict__ resid,
    float* __restrict__ C, int ldc,
    const int* __restrict__ rowlist,
    const int* __restrict__ cnt)
{
    __shared__ unsigned As[2][128*20];
    __shared__ unsigned Bs[2][16*136];
    __shared__ int rowsS[128];

    if (GATHER) {
        int e = blockIdx.z;
        Bm      += (size_t)e * K * N;
        bias    += (size_t)e * N;
        rowlist += (size_t)e * CAP;
        cnt     += e;
    }
    int m0 = blockIdx.y * 128, n0 = blockIdx.x * 128;
    int tid = threadIdx.x, lane = tid & 31, wid = tid >> 5;
    int warpM = wid & 3, warpN = wid >> 2;

    if (GATHER) {
        int Meff = *cnt;
        if (m0 >= Meff) return;
        if (tid < 128) {
            int gidx = m0 + tid;
            rowsS[tid] = (gidx < Meff) ? rowlist[gidx] : -1;
        }
        __syncthreads();
    }

    // A loader: one thread loads 8 consecutive k of one row: m = tid>>1, kb = (tid&1)*8
    int lm  = tid >> 1;
    int lkb = (tid & 1) << 3;
    const float* Aptr;
    if (GATHER) {
        int pr = rowsS[lm];
        Aptr = (pr < 0) ? nullptr
                        : A + (size_t)(AROW_PAIR ? pr : (pr >> 1)) * lda + lkb;
    } else {
        Aptr = A + (size_t)(m0 + lm) * lda + lkb;
    }
    // B loader: k = tid>>5 (and +8), n = (tid&31)*4
    int lbk = tid >> 5;
    int lbn = (tid & 31) << 2;
    const float* Bptr = Bm + (size_t)lbk * N + n0 + lbn;

    float acc[2][8][4];
    #pragma unroll
    for (int i = 0; i < 2; i++)
        #pragma unroll
        for (int j = 0; j < 8; j++)
            #pragma unroll
            for (int q = 0; q < 4; q++) acc[i][j][q] = 0.f;

    float4 ra0, ra1, rb0, rb1;

    auto loadg = [&](int k0) {
        if (Aptr) {
            ra0 = *(const float4*)(Aptr + k0);
            ra1 = *(const float4*)(Aptr + k0 + 4);
        } else {
            ra0 = make_float4(0,0,0,0); ra1 = ra0;
        }
        rb0 = *(const float4*)(Bptr + (size_t)k0 * N);
        rb1 = *(const float4*)(Bptr + (size_t)(k0 + 8) * N);
    };
    auto stores = [&](int buf) {
        unsigned* ap = &As[buf][lm*20 + lkb];
        ap[0]=f2tf32(ra0.x); ap[1]=f2tf32(ra0.y); ap[2]=f2tf32(ra0.z); ap[3]=f2tf32(ra0.w);
        ap[4]=f2tf32(ra1.x); ap[5]=f2tf32(ra1.y); ap[6]=f2tf32(ra1.z); ap[7]=f2tf32(ra1.w);
        unsigned* bp0 = &Bs[buf][lbk*136 + lbn];
        bp0[0]=f2tf32(rb0.x); bp0[1]=f2tf32(rb0.y); bp0[2]=f2tf32(rb0.z); bp0[3]=f2tf32(rb0.w);
        unsigned* bp1 = &Bs[buf][(lbk+8)*136 + lbn];
        bp1[0]=f2tf32(rb1.x); bp1[1]=f2tf32(rb1.y); bp1[2]=f2tf32(rb1.z); bp1[3]=f2tf32(rb1.w);
    };
    auto compute = [&](int buf) {
        const unsigned* Asb = As[buf];
        const unsigned* Bsb = Bs[buf];
        #pragma unroll
        for (int kk = 0; kk < 16; kk += 8) {
            int kc = kk + (lane & 3);
            unsigned af[2][4];
            #pragma unroll
            for (int mt = 0; mt < 2; mt++) {
                int r = warpM*32 + mt*16 + (lane >> 2);
                af[mt][0] = Asb[r*20 + kc];
                af[mt][1] = Asb[(r+8)*20 + kc];
                af[mt][2] = Asb[r*20 + kc + 4];
                af[mt][3] = Asb[(r+8)*20 + kc + 4];
            }
            unsigned bf[8][2];
            #pragma unroll
            for (int nt = 0; nt < 8; nt++) {
                int c = warpN*64 + nt*8 + (lane >> 2);
                bf[nt][0] = Bsb[kc*136 + c];
                bf[nt][1] = Bsb[(kc+4)*136 + c];
            }
            #pragma unroll
            for (int mt = 0; mt < 2; mt++)
                #pragma unroll
                for (int nt = 0; nt < 8; nt++)
                    mma_tf32(acc[mt][nt], af[mt], bf[nt]);
        }
    };

    loadg(0);
    stores(0);
    __syncthreads();
    int buf = 0;
    for (int k0 = 0; k0 < K; k0 += 16) {
        bool more = (k0 + 16) < K;
        if (more) loadg(k0 + 16);
        compute(buf);
        if (more) {
            stores(buf ^ 1);
            __syncthreads();
            buf ^= 1;
        }
    }

    // epilogue
    #pragma unroll
    for (int mt = 0; mt < 2; mt++) {
        int rr0 = warpM*32 + mt*16 + (lane >> 2);
        #pragma unroll
        for (int half = 0; half < 2; half++) {
            int rloc = rr0 + half*8;
            int crow;
            if (GATHER) {
                int pr = rowsS[rloc];
                if (pr < 0) continue;
                crow = pr;
            } else {
                crow = m0 + rloc;
            }
            #pragma unroll
            for (int nt = 0; nt < 8; nt++) {
                int col = n0 + warpN*64 + nt*8 + (lane & 3)*2;
                float v0 = acc[mt][nt][half*2 + 0] + bias[col];
                float v1 = acc[mt][nt][half*2 + 1] + bias[col + 1];
                if (RELU) { v0 = fmaxf(v0, 0.f); v1 = fmaxf(v1, 0.f); }
                if (RESID) {
                    const float* rp = resid + (size_t)crow*ldc + col;
                    v0 += rp[0]; v1 += rp[1];
                }
                *(float2*)(C + (size_t)crow*ldc + col) = make_float2(v0, v1);
            }
        }
    }
}

// ---------------- flash attention (causal), one q-row per thread ----------------
__global__ void __launch_bounds__(128, 1) attn_kernel(
    const float* __restrict__ q, const float* __restrict__ k,
    const float* __restrict__ v, float* __restrict__ ctx)
{
    int qt = blockIdx.x, h = blockIdx.y, b = blockIdx.z;
    int tid = threadIdx.x;
    int qidx = qt * 128 + tid;

    __shared__ float4 ksh[32*16];
    __shared__ float4 vsh[32*16];

    float4 qr[16], acc[16];
    const float4* qp = (const float4*)(q + (size_t)(b*SS + qidx)*DDIM + h*DH);
    #pragma unroll
    for (int j = 0; j < 16; j++) {
        float4 t = qp[j];
        qr[j] = make_float4(t.x*0.125f, t.y*0.125f, t.z*0.125f, t.w*0.125f);
        acc[j] = make_float4(0,0,0,0);
    }
    float m = -3.0e38f, l = 0.f;

    int kend = qt*128 + 128;
    if (kend > SS) kend = SS;
    for (int kt = 0; kt < kend; kt += 32) {
        __syncthreads();
        for (int i = tid; i < 512; i += 128) {
            int r = i >> 4, c = i & 15;
            size_t base = (size_t)(b*SS + kt + r)*DDIM + h*DH;
            ksh[i] = *((const float4*)(k + base) + c);
            vsh[i] = *((const float4*)(v + base) + c);
        }
        __syncthreads();

        float s[32];
        float tm = -3.0e38f;
        #pragma unroll
        for (int kk = 0; kk < 32; kk++) {
            const float4* kr = &ksh[kk*16];
            float d = 0.f;
            #pragma unroll
            for (int j = 0; j < 16; j++) {
                float4 kv = kr[j];
                d += qr[j].x*kv.x + qr[j].y*kv.y + qr[j].z*kv.z + qr[j].w*kv.w;
            }
            s[kk] = (kt + kk <= qidx) ? d : -1e9f;
            tm = fmaxf(tm, s[kk]);
        }
        float nm = fmaxf(m, tm);
        float c = __expf(m - nm);
        l *= c;
        #pragma unroll
        for (int j = 0; j < 16; j++) {
            acc[j].x *= c; acc[j].y *= c; acc[j].z *= c; acc[j].w *= c;
        }
        #pragma unroll
        for (int kk = 0; kk < 32; kk++) {
            float p = __expf(s[kk] - nm);
            l += p;
            const float4* vr = &vsh[kk*16];
            #pragma unroll
            for (int j = 0; j < 16; j++) {
                float4 vv = vr[j];
                acc[j].x += p*vv.x; acc[j].y += p*vv.y;
                acc[j].z += p*vv.z; acc[j].w += p*vv.w;
            }
        }
        m = nm;
    }
    float inv = 1.f / l;
    float4* op = (float4*)(ctx + (size_t)(b*SS + qidx)*DDIM + h*DH);
    #pragma unroll
    for (int j = 0; j < 16; j++)
        op[j] = make_float4(acc[j].x*inv, acc[j].y*inv, acc[j].z*inv, acc[j].w*inv);
}

// ---------------- gate ----------------
__global__ void zero_cnt_kernel(int* cnt) {
    if (threadIdx.x < EE) cnt[threadIdx.x] = 0;
}

__global__ void gate_kernel(const float* __restrict__ h, const float* __restrict__ gw,
                            const float* __restrict__ gb, float* __restrict__ sc,
                            int* __restrict__ cnt, int* __restrict__ list)
{
    int warp = (blockIdx.x * blockDim.x + threadIdx.x) >> 5;
    if (warp >= NTOK) return;
    int lane = threadIdx.x & 31;
    float a[8] = {0,0,0,0,0,0,0,0};
    const float* hr = h + (size_t)warp * DDIM;
    for (int d = lane; d < DDIM; d += 32) {
        float hv = hr[d];
        float4 w0 = *(const float4*)(gw + (size_t)d*EE);
        float4 w1 = *(const float4*)(gw + (size_t)d*EE + 4);
        a[0]+=hv*w0.x; a[1]+=hv*w0.y; a[2]+=hv*w0.z; a[3]+=hv*w0.w;
        a[4]+=hv*w1.x; a[5]+=hv*w1.y; a[6]+=hv*w1.z; a[7]+=hv*w1.w;
    }
    #pragma unroll
    for (int e = 0; e < 8; e++)
        #pragma unroll
        for (int o = 16; o > 0; o >>= 1)
            a[e] += __shfl_down_sync(0xffffffffu, a[e], o);
    if (lane == 0) {
        float lg[8];
        #pragma unroll
        for (int e = 0; e < 8; e++) lg[e] = a[e] + gb[e];
        int i0 = 0; float v0 = lg[0];
        #pragma unroll
        for (int e = 1; e < 8; e++) if (lg[e] > v0) { v0 = lg[e]; i0 = e; }
        int i1 = -1; float v1 = -3.0e38f;
        #pragma unroll
        for (int e = 0; e < 8; e++) if (e != i0 && lg[e] > v1) { v1 = lg[e]; i1 = e; }
        float e1 = __expf(v1 - v0);
        float s0 = 1.f / (1.f + e1);
        float s1 = e1 * s0;
        sc[2*warp]   = s0;
        sc[2*warp+1] = s1;
        int p0 = atomicAdd(&cnt[i0], 1);
        list[(size_t)i0*CAP + p0] = 2*warp;
        int p1 = atomicAdd(&cnt[i1], 1);
        list[(size_t)i1*CAP + p1] = 2*warp + 1;
    }
}

// ---------------- combine ----------------
__global__ void combine_kernel(const float* __restrict__ h, const float* __restrict__ o2,
                               const float* __restrict__ sc, const float* __restrict__ xa,
                               const float* __restrict__ g, const float* __restrict__ b,
                               float* __restrict__ out)
{
    int t = blockIdx.x;
    const float* hr = h + (size_t)t*DDIM;
    const float* r0 = o2 + (size_t)(2*t)*DDIM;
    const float* r1 = o2 + (size_t)(2*t+1)*DDIM;
    float s0 = sc[2*t], s1 = sc[2*t+1];
    float tv[3];
    float s = 0.f;
    #pragma unroll
    for (int i = 0; i < 3; i++) {
        int d = threadIdx.x + i*256;
        tv[i] = hr[d] + s0*r0[d] + s1*r1[d];
        s += tv[i];
    }
    s = blockReduceSum(s);
    float mean = s * (1.f / DDIM);
    float vs = 0.f;
    #pragma unroll
    for (int i = 0; i < 3; i++) { float d = tv[i] - mean; vs += d*d; }
    vs = blockReduceSum(vs);
    float rstd = rsqrtf(vs * (1.f / DDIM) + 1e-5f);
    #pragma unroll
    for (int i = 0; i < 3; i++) {
        int d = threadIdx.x + i*256;
        out[(size_t)t*DDIM + d] = xa[(size_t)t*DDIM + d] + (tv[i] - mean)*rstd*g[d] + b[d];
    }
}

// ---------------- launch ----------------
extern "C" void kernel_launch(void* const* d_in, const int* in_sizes, int n_in,
                              void* d_out, int out_size)
{
    const float* x        = (const float*)d_in[0];
    const float* ln_a_g   = (const float*)d_in[2];
    const float* ln_a_b   = (const float*)d_in[3];
    const float* wq       = (const float*)d_in[4];
    const float* bq       = (const float*)d_in[5];
    const float* wk       = (const float*)d_in[6];
    const float* bk       = (const float*)d_in[7];
    const float* wv       = (const float*)d_in[8];
    const float* bv       = (const float*)d_in[9];
    const float* wo       = (const float*)d_in[10];
    const float* bo       = (const float*)d_in[11];
    const float* ln_f_g   = (const float*)d_in[12];
    const float* ln_f_b   = (const float*)d_in[13];
    const float* gate_w   = (const float*)d_in[14];
    const float* gate_b   = (const float*)d_in[15];
    const float* w1       = (const float*)d_in[16];
    const float* b1       = (const float*)d_in[17];
    const float* w2       = (const float*)d_in[18];
    const float* b2       = (const float*)d_in[19];
    const float* moe_g    = (const float*)d_in[20];
    const float* moe_b    = (const float*)d_in[21];
    float* out = (float*)d_out;

    float *a, *qb, *kb, *vb, *ctx, *xa, *h, *y1, *o2, *sc;
    int *cnt, *list;
    cudaGetSymbolAddress((void**)&a,   g_a);
    cudaGetSymbolAddress((void**)&qb,  g_q);
    cudaGetSymbolAddress((void**)&kb,  g_k);
    cudaGetSymbolAddress((void**)&vb,  g_v);
    cudaGetSymbolAddress((void**)&ctx, g_ctx);
    cudaGetSymbolAddress((void**)&xa,  g_xa);
    cudaGetSymbolAddress((void**)&h,   g_h);
    cudaGetSymbolAddress((void**)&y1,  g_y1);
    cudaGetSymbolAddress((void**)&o2,  g_o2);
    cudaGetSymbolAddress((void**)&sc,  g_sc);
    cudaGetSymbolAddress((void**)&cnt, g_cnt);
    cudaGetSymbolAddress((void**)&list,g_list);

    // 1) a = ln_attn(x)
    ln_kernel<<<NTOK, 256>>>(x, ln_a_g, ln_a_b, a);

    // 2) q,k,v projections (tf32 tensor cores)
    dim3 gQKV(DDIM/128, NTOK/128, 1);
    tgemm_k<false,false,false,false><<<gQKV, 256>>>(NTOK, DDIM, DDIM, a, DDIM, wq, bq, nullptr, qb, DDIM, nullptr, nullptr);
    tgemm_k<false,false,false,false><<<gQKV, 256>>>(NTOK, DDIM, DDIM, a, DDIM, wk, bk, nullptr, kb, DDIM, nullptr, nullptr);
    tgemm_k<false,false,false,false><<<gQKV, 256>>>(NTOK, DDIM, DDIM, a, DDIM, wv, bv, nullptr, vb, DDIM, nullptr, nullptr);

    // 3) flash attention (causal)
    attn_kernel<<<dim3(SS/128, HH, BB), 128>>>(qb, kb, vb, ctx);

    // 4) xa = x + ctx @ wo + bo
    tgemm_k<false,false,false,true><<<gQKV, 256>>>(NTOK, DDIM, DDIM, ctx, DDIM, wo, bo, x, xa, DDIM, nullptr, nullptr);

    // 5) h = ln_ff(xa)
    ln_kernel<<<NTOK, 256>>>(xa, ln_f_g, ln_f_b, h);

    // 6) gate: top-2 per token + per-expert pair lists
    zero_cnt_kernel<<<1, 32>>>(cnt);
    gate_kernel<<<NTOK/8, 256>>>(h, gate_w, gate_b, sc, cnt, list);

    // 7) expert GEMM1: y1[pair] = relu(h[token] @ w1[e] + b1[e])
    tgemm_k<true,false,true,false><<<dim3(HID/128, CAP/128, EE), 256>>>(
        CAP, HID, DDIM, h, DDIM, w1, b1, nullptr, y1, HID, list, cnt);

    // 8) expert GEMM2: o2[pair] = y1[pair] @ w2[e] + b2[e]
    tgemm_k<true,true,false,false><<<dim3(DDIM/128, CAP/128, EE), 256>>>(
        CAP, DDIM, HID, y1, HID, w2, b2, nullptr, o2, DDIM, list, cnt);

    // 9) combine + post-LN + final residual
    combine_kernel<<<NTOK, 256>>>(h, o2, sc, xa, moe_g, moe_b, out);
}

// round 4
// speedup vs baseline: 2.3146x; 1.0048x over previous
#include <cuda_runtime.h>

#define BB 4
#define SS 1024
#define DDIM 768
#define HH 12
#define EE 8
#define HID 3072
#define DH 64
#define NTOK (BB*SS)
#define CAP (NTOK*2)

// ---------------- scratch (device globals: no allocation allowed) ----------------
__device__ float g_a[NTOK*DDIM];     // ln_attn(x)
__device__ float g_q[NTOK*DDIM];
__device__ float g_k[NTOK*DDIM];
__device__ float g_v[NTOK*DDIM];
__device__ float g_ctx[NTOK*DDIM];
__device__ float g_xa[NTOK*DDIM];    // x + attn_out
__device__ float g_h[NTOK*DDIM];     // ln_ff(xa)
__device__ float g_y1[CAP*HID];      // expert hidden (per token-slot pair)
__device__ float g_o2[CAP*DDIM];     // expert out (per pair)
__device__ float g_sc[CAP];          // top-2 softmax weights (per pair)
__device__ int   g_cnt[EE];
__device__ int   g_list[EE*CAP];

// ---------------- helpers ----------------
__device__ __forceinline__ unsigned f2tf32(float x) {
    unsigned u; asm("cvt.rna.tf32.f32 %0, %1;" : "=r"(u) : "f"(x)); return u;
}

__device__ __forceinline__ void mma_tf32(float c[4], const unsigned a[4], const unsigned b[2]) {
    asm volatile("mma.sync.aligned.m16n8k8.row.col.f32.tf32.tf32.f32 "
        "{%0,%1,%2,%3}, {%4,%5,%6,%7}, {%8,%9}, {%0,%1,%2,%3};"
        : "+f"(c[0]), "+f"(c[1]), "+f"(c[2]), "+f"(c[3])
        : "r"(a[0]), "r"(a[1]), "r"(a[2]), "r"(a[3]), "r"(b[0]), "r"(b[1]));
}

__device__ __forceinline__ float blockReduceSum(float v) {
    __shared__ float sh[33];
    __syncthreads();
    int lane = threadIdx.x & 31, wid = threadIdx.x >> 5;
    #pragma unroll
    for (int o = 16; o > 0; o >>= 1) v += __shfl_down_sync(0xffffffffu, v, o);
    if (lane == 0) sh[wid] = v;
    __syncthreads();
    float r = (threadIdx.x < (blockDim.x >> 5)) ? sh[threadIdx.x] : 0.f;
    if (wid == 0) {
        #pragma unroll
        for (int o = 16; o > 0; o >>= 1) r += __shfl_down_sync(0xffffffffu, r, o);
        if (lane == 0) sh[32] = r;
    }
    __syncthreads();
    return sh[32];
}

// ---------------- layernorm ----------------
__global__ void ln_kernel(const float* __restrict__ x, const float* __restrict__ g,
                          const float* __restrict__ b, float* __restrict__ out) {
    int row = blockIdx.x;
    const float* xr = x + (size_t)row * DDIM;
    float v[3];
    float s = 0.f;
    #pragma unroll
    for (int i = 0; i < 3; i++) { v[i] = xr[threadIdx.x + i*256]; s += v[i]; }
    s = blockReduceSum(s);
    float mean = s * (1.f / DDIM);
    float vs = 0.f;
    #pragma unroll
    for (int i = 0; i < 3; i++) { float d = v[i] - mean; vs += d*d; }
    vs = blockReduceSum(vs);
    float rstd = rsqrtf(vs * (1.f / DDIM) + 1e-5f);
    #pragma unroll
    for (int i = 0; i < 3; i++) {
        int d = threadIdx.x + i*256;
        out[(size_t)row*DDIM + d] = (v[i] - mean) * rstd * g[d] + b[d];
    }
}

// ---------------- TF32 tensor-core GEMM ----------------
// 128x128 block tile, BK=16, 8 warps (4 along M x 2 along N), warp tile 32x64.
// A: [M][K] row-major (optionally gathered rows). B: [K][N] row-major.
// Shared: As[m][k] pad 20, Bs[k][n] pad 136 (conflict-free fragment loads).
template<bool GATHER, bool AROW_PAIR, bool RELU, bool RESID>
__global__ __launch_bounds__(256, 2) void tgemm_k(
    int M, int N, int K,
    const float* __restrict__ A, int lda,
    const float* __restrict__ Bm,
    const float* __restrict__ bias,
    const float* __restrict__ resid,
    float* __restrict__ C, int ldc,
    const int* __restrict__ rowlist,
    const int* __restrict__ cnt)
{
    __shared__ unsigned As[2][128*20];
    __shared__ unsigned Bs[2][16*136];
    __shared__ int rowsS[128];

    if (GATHER) {
        int e = blockIdx.z;
        Bm      += (size_t)e * K * N;
        bias    += (size_t)e * N;
        rowlist += (size_t)e * CAP;
        cnt     += e;
    }
    int m0 = blockIdx.y * 128, n0 = blockIdx.x * 128;
    int tid = threadIdx.x, lane = tid & 31, wid = tid >> 5;
    int warpM = wid & 3, warpN = wid >> 2;

    if (GATHER) {
        int Meff = *cnt;
        if (m0 >= Meff) return;
        if (tid < 128) {
            int gidx = m0 + tid;
            rowsS[tid] = (gidx < Meff) ? rowlist[gidx] : -1;
        }
        __syncthreads();
    }

    // A loader: one thread loads 8 consecutive k of one row: m = tid>>1, kb = (tid&1)*8
    int lm  = tid >> 1;
    int lkb = (tid & 1) << 3;
    const float* Aptr;
    if (GATHER) {
        int pr = rowsS[lm];
        Aptr = (pr < 0) ? nullptr
                        : A + (size_t)(AROW_PAIR ? pr : (pr >> 1)) * lda + lkb;
    } else {
        Aptr = A + (size_t)(m0 + lm) * lda + lkb;
    }
    // B loader: k = tid>>5 (and +8), n = (tid&31)*4
    int lbk = tid >> 5;
    int lbn = (tid & 31) << 2;
    const float* Bptr = Bm + (size_t)lbk * N + n0 + lbn;

    float acc[2][8][4];
    #pragma unroll
    for (int i = 0; i < 2; i++)
        #pragma unroll
        for (int j = 0; j < 8; j++)
            #pragma unroll
            for (int q = 0; q < 4; q++) acc[i][j][q] = 0.f;

    float4 ra0, ra1, rb0, rb1;

    auto loadg = [&](int k0) {
        if (Aptr) {
            ra0 = *(const float4*)(Aptr + k0);
            ra1 = *(const float4*)(Aptr + k0 + 4);
        } else {
            ra0 = make_float4(0,0,0,0); ra1 = ra0;
        }
        rb0 = *(const float4*)(Bptr + (size_t)k0 * N);
        rb1 = *(const float4*)(Bptr + (size_t)(k0 + 8) * N);
    };
    auto stores = [&](int buf) {
        unsigned* ap = &As[buf][lm*20 + lkb];
        ap[0]=f2tf32(ra0.x); ap[1]=f2tf32(ra0.y); ap[2]=f2tf32(ra0.z); ap[3]=f2tf32(ra0.w);
        ap[4]=f2tf32(ra1.x); ap[5]=f2tf32(ra1.y); ap[6]=f2tf32(ra1.z); ap[7]=f2tf32(ra1.w);
        unsigned* bp0 = &Bs[buf][lbk*136 + lbn];
        bp0[0]=f2tf32(rb0.x); bp0[1]=f2tf32(rb0.y); bp0[2]=f2tf32(rb0.z); bp0[3]=f2tf32(rb0.w);
        unsigned* bp1 = &Bs[buf][(lbk+8)*136 + lbn];
        bp1[0]=f2tf32(rb1.x); bp1[1]=f2tf32(rb1.y); bp1[2]=f2tf32(rb1.z); bp1[3]=f2tf32(rb1.w);
    };
    auto compute = [&](int buf) {
        const unsigned* Asb = As[buf];
        const unsigned* Bsb = Bs[buf];
        #pragma unroll
        for (int kk = 0; kk < 16; kk += 8) {
            int kc = kk + (lane & 3);
            unsigned af[2][4];
            #pragma unroll
            for (int mt = 0; mt < 2; mt++) {
                int r = warpM*32 + mt*16 + (lane >> 2);
                af[mt][0] = Asb[r*20 + kc];
                af[mt][1] = Asb[(r+8)*20 + kc];
                af[mt][2] = Asb[r*20 + kc + 4];
                af[mt][3] = Asb[(r+8)*20 + kc + 4];
            }
            unsigned bf[8][2];
            #pragma unroll
            for (int nt = 0; nt < 8; nt++) {
                int c = warpN*64 + nt*8 + (lane >> 2);
                bf[nt][0] = Bsb[kc*136 + c];
                bf[nt][1] = Bsb[(kc+4)*136 + c];
            }
            #pragma unroll
            for (int mt = 0; mt < 2; mt++)
                #pragma unroll
                for (int nt = 0; nt < 8; nt++)
                    mma_tf32(acc[mt][nt], af[mt], bf[nt]);
        }
    };

    loadg(0);
    stores(0);
    __syncthreads();
    int buf = 0;
    for (int k0 = 0; k0 < K; k0 += 16) {
        bool more = (k0 + 16) < K;
        if (more) loadg(k0 + 16);
        compute(buf);
        if (more) {
            stores(buf ^ 1);
            __syncthreads();
            buf ^= 1;
        }
    }

    // epilogue
    #pragma unroll
    for (int mt = 0; mt < 2; mt++) {
        int rr0 = warpM*32 + mt*16 + (lane >> 2);
        #pragma unroll
        for (int half = 0; half < 2; half++) {
            int rloc = rr0 + half*8;
            int crow;
            if (GATHER) {
                int pr = rowsS[rloc];
                if (pr < 0) continue;
                crow = pr;
            } else {
                crow = m0 + rloc;
            }
            #pragma unroll
            for (int nt = 0; nt < 8; nt++) {
                int col = n0 + warpN*64 + nt*8 + (lane & 3)*2;
                float v0 = acc[mt][nt][half*2 + 0] + bias[col];
                float v1 = acc[mt][nt][half*2 + 1] + bias[col + 1];
                if (RELU) { v0 = fmaxf(v0, 0.f); v1 = fmaxf(v1, 0.f); }
                if (RESID) {
                    const float* rp = resid + (size_t)crow*ldc + col;
                    v0 += rp[0]; v1 += rp[1];
                }
                *(float2*)(C + (size_t)crow*ldc + col) = make_float2(v0, v1);
            }
        }
    }
}

// ---------------- flash attention (causal), one q-row per thread ----------------
__global__ void __launch_bounds__(128, 1) attn_kernel(
    const float* __restrict__ q, const float* __restrict__ k,
    const float* __restrict__ v, float* __restrict__ ctx)
{
    int qt = blockIdx.x, h = blockIdx.y, b = blockIdx.z;
    int tid = threadIdx.x;
    int qidx = qt * 128 + tid;

    __shared__ float4 ksh[32*16];
    __shared__ float4 vsh[32*16];

    float4 qr[16], acc[16];
    const float4* qp = (const float4*)(q + (size_t)(b*SS + qidx)*DDIM + h*DH);
    #pragma unroll
    for (int j = 0; j < 16; j++) {
        float4 t = qp[j];
        qr[j] = make_float4(t.x*0.125f, t.y*0.125f, t.z*0.125f, t.w*0.125f);
        acc[j] = make_float4(0,0,0,0);
    }
    float m = -3.0e38f, l = 0.f;

    int kend = qt*128 + 128;
    if (kend > SS) kend = SS;
    for (int kt = 0; kt < kend; kt += 32) {
        __syncthreads();
        for (int i = tid; i < 512; i += 128) {
            int r = i >> 4, c = i & 15;
            size_t base = (size_t)(b*SS + kt + r)*DDIM + h*DH;
            ksh[i] = *((const float4*)(k + base) + c);
            vsh[i] = *((const float4*)(v + base) + c);
        }
        __syncthreads();

        float s[32];
        float tm = -3.0e38f;
        #pragma unroll
        for (int kk = 0; kk < 32; kk++) {
            const float4* kr = &ksh[kk*16];
            float d = 0.f;
            #pragma unroll
            for (int j = 0; j < 16; j++) {
                float4 kv = kr[j];
                d += qr[j].x*kv.x + qr[j].y*kv.y + qr[j].z*kv.z + qr[j].w*kv.w;
            }
            s[kk] = (kt + kk <= qidx) ? d : -1e9f;
            tm = fmaxf(tm, s[kk]);
        }
        float nm = fmaxf(m, tm);
        float c = __expf(m - nm);
        l *= c;
        #pragma unroll
        for (int j = 0; j < 16; j++) {
            acc[j].x *= c; acc[j].y *= c; acc[j].z *= c; acc[j].w *= c;
        }
        #pragma unroll
        for (int kk = 0; kk < 32; kk++) {
            float p = __expf(s[kk] - nm);
            l += p;
            const float4* vr = &vsh[kk*16];
            #pragma unroll
            for (int j = 0; j < 16; j++) {
                float4 vv = vr[j];
                acc[j].x += p*vv.x; acc[j].y += p*vv.y;
                acc[j].z += p*vv.z; acc[j].w += p*vv.w;
            }
        }
        m = nm;
    }
    float inv = 1.f / l;
    float4* op = (float4*)(ctx + (size_t)(b*SS + qidx)*DDIM + h*DH);
    #pragma unroll
    for (int j = 0; j < 16; j++)
        op[j] = make_float4(acc[j].x*inv, acc[j].y*inv, acc[j].z*inv, acc[j].w*inv);
}

// ---------------- gate ----------------
__global__ void zero_cnt_kernel(int* cnt) {
    if (threadIdx.x < EE) cnt[threadIdx.x] = 0;
}

__global__ void gate_kernel(const float* __restrict__ h, const float* __restrict__ gw,
                            const float* __restrict__ gb, float* __restrict__ sc,
                            int* __restrict__ cnt, int* __restrict__ list)
{
    int warp = (blockIdx.x * blockDim.x + threadIdx.x) >> 5;
    if (warp >= NTOK) return;
    int lane = threadIdx.x & 31;
    float a[8] = {0,0,0,0,0,0,0,0};
    const float* hr = h + (size_t)warp * DDIM;
    for (int d = lane; d < DDIM; d += 32) {
        float hv = hr[d];
        float4 w0 = *(const float4*)(gw + (size_t)d*EE);
        float4 w1 = *(const float4*)(gw + (size_t)d*EE + 4);
        a[0]+=hv*w0.x; a[1]+=hv*w0.y; a[2]+=hv*w0.z; a[3]+=hv*w0.w;
        a[4]+=hv*w1.x; a[5]+=hv*w1.y; a[6]+=hv*w1.z; a[7]+=hv*w1.w;
    }
    #pragma unroll
    for (int e = 0; e < 8; e++)
        #pragma unroll
        for (int o = 16; o > 0; o >>= 1)
            a[e] += __shfl_down_sync(0xffffffffu, a[e], o);
    if (lane == 0) {
        float lg[8];
        #pragma unroll
        for (int e = 0; e < 8; e++) lg[e] = a[e] + gb[e];
        int i0 = 0; float v0 = lg[0];
        #pragma unroll
        for (int e = 1; e < 8; e++) if (lg[e] > v0) { v0 = lg[e]; i0 = e; }
        int i1 = -1; float v1 = -3.0e38f;
        #pragma unroll
        for (int e = 0; e < 8; e++) if (e != i0 && lg[e] > v1) { v1 = lg[e]; i1 = e; }
        float e1 = __expf(v1 - v0);
        float s0 = 1.f / (1.f + e1);
        float s1 = e1 * s0;
        sc[2*warp]   = s0;
        sc[2*warp+1] = s1;
        int p0 = atomicAdd(&cnt[i0], 1);
        list[(size_t)i0*CAP + p0] = 2*warp;
        int p1 = atomicAdd(&cnt[i1], 1);
        list[(size_t)i1*CAP + p1] = 2*warp + 1;
    }
}

// ---------------- combine ----------------
__global__ void combine_kernel(const float* __restrict__ h, const float* __restrict__ o2,
                               const float* __restrict__ sc, const float* __restrict__ xa,
                               const float* __restrict__ g, const float* __restrict__ b,
                               float* __restrict__ out)
{
    int t = blockIdx.x;
    const float* hr = h + (size_t)t*DDIM;
    const float* r0 = o2 + (size_t)(2*t)*DDIM;
    const float* r1 = o2 + (size_t)(2*t+1)*DDIM;
    float s0 = sc[2*t], s1 = sc[2*t+1];
    float tv[3];
    float s = 0.f;
    #pragma unroll
    for (int i = 0; i < 3; i++) {
        int d = threadIdx.x + i*256;
        tv[i] = hr[d] + s0*r0[d] + s1*r1[d];
        s += tv[i];
    }
    s = blockReduceSum(s);
    float mean = s * (1.f / DDIM);
    float vs = 0.f;
    #pragma unroll
    for (int i = 0; i < 3; i++) { float d = tv[i] - mean; vs += d*d; }
    vs = blockReduceSum(vs);
    float rstd = rsqrtf(vs * (1.f / DDIM) + 1e-5f);
    #pragma unroll
    for (int i = 0; i < 3; i++) {
        int d = threadIdx.x + i*256;
        out[(size_t)t*DDIM + d] = xa[(size_t)t*DDIM + d] + (tv[i] - mean)*rstd*g[d] + b[d];
    }
}

// ---------------- launch ----------------
extern "C" void kernel_launch(void* const* d_in, const int* in_sizes, int n_in,
                              void* d_out, int out_size)
{
    const float* x        = (const float*)d_in[0];
    const float* ln_a_g   = (const float*)d_in[2];
    const float* ln_a_b   = (const float*)d_in[3];
    const float* wq       = (const float*)d_in[4];
    const float* bq       = (const float*)d_in[5];
    const float* wk       = (const float*)d_in[6];
    const float* bk       = (const float*)d_in[7];
    const float* wv       = (const float*)d_in[8];
    const float* bv       = (const float*)d_in[9];
    const float* wo       = (const float*)d_in[10];
    const float* bo       = (const float*)d_in[11];
    const float* ln_f_g   = (const float*)d_in[12];
    const float* ln_f_b   = (const float*)d_in[13];
    const float* gate_w   = (const float*)d_in[14];
    const float* gate_b   = (const float*)d_in[15];
    const float* w1       = (const float*)d_in[16];
    const float* b1       = (const float*)d_in[17];
    const float* w2       = (const float*)d_in[18];
    const float* b2       = (const float*)d_in[19];
    const float* moe_g    = (const float*)d_in[20];
    const float* moe_b    = (const float*)d_in[21];
    float* out = (float*)d_out;

    float *a, *qb, *kb, *vb, *ctx, *xa, *h, *y1, *o2, *sc;
    int *cnt, *list;
    cudaGetSymbolAddress((void**)&a,   g_a);
    cudaGetSymbolAddress((void**)&qb,  g_q);
    cudaGetSymbolAddress((void**)&kb,  g_k);
    cudaGetSymbolAddress((void**)&vb,  g_v);
    cudaGetSymbolAddress((void**)&ctx, g_ctx);
    cudaGetSymbolAddress((void**)&xa,  g_xa);
    cudaGetSymbolAddress((void**)&h,   g_h);
    cudaGetSymbolAddress((void**)&y1,  g_y1);
    cudaGetSymbolAddress((void**)&o2,  g_o2);
    cudaGetSymbolAddress((void**)&sc,  g_sc);
    cudaGetSymbolAddress((void**)&cnt, g_cnt);
    cudaGetSymbolAddress((void**)&list,g_list);

    // 1) a = ln_attn(x)
    ln_kernel<<<NTOK, 256>>>(x, ln_a_g, ln_a_b, a);

    // 2) q,k,v projections (tf32 tensor cores)
    dim3 gQKV(DDIM/128, NTOK/128, 1);
    tgemm_k<false,false,false,false><<<gQKV, 256>>>(NTOK, DDIM, DDIM, a, DDIM, wq, bq, nullptr, qb, DDIM, nullptr, nullptr);
    tgemm_k<false,false,false,false><<<gQKV, 256>>>(NTOK, DDIM, DDIM, a, DDIM, wk, bk, nullptr, kb, DDIM, nullptr, nullptr);
    tgemm_k<false,false,false,false><<<gQKV, 256>>>(NTOK, DDIM, DDIM, a, DDIM, wv, bv, nullptr, vb, DDIM, nullptr, nullptr);

    // 3) flash attention (causal)
    attn_kernel<<<dim3(SS/128, HH, BB), 128>>>(qb, kb, vb, ctx);

    // 4) xa = x + ctx @ wo + bo
    tgemm_k<false,false,false,true><<<gQKV, 256>>>(NTOK, DDIM, DDIM, ctx, DDIM, wo, bo, x, xa, DDIM, nullptr, nullptr);

    // 5) h = ln_ff(xa)
    ln_kernel<<<NTOK, 256>>>(xa, ln_f_g, ln_f_b, h);

    // 6) gate: top-2 per token + per-expert pair lists
    zero_cnt_kernel<<<1, 32>>>(cnt);
    gate_kernel<<<NTOK/8, 256>>>(h, gate_w, gate_b, sc, cnt, list);

    // 7) expert GEMM1: y1[pair] = relu(h[token] @ w1[e] + b1[e])
    tgemm_k<true,false,true,false><<<dim3(HID/128, CAP/128, EE), 256>>>(
        CAP, HID, DDIM, h, DDIM, w1, b1, nullptr, y1, HID, list, cnt);

    // 8) expert GEMM2: o2[pair] = y1[pair] @ w2[e] + b2[e]
    tgemm_k<true,true,false,false><<<dim3(DDIM/128, CAP/128, EE), 256>>>(
        CAP, DDIM, HID, y1, HID, w2, b2, nullptr, o2, DDIM, list, cnt);

    // 9) combine + post-LN + final residual
    combine_kernel<<<NTOK, 256>>>(h, o2, sc, xa, moe_g, moe_b, out);
}